// round 14
// baseline (speedup 1.0000x reference)
#include <cuda_runtime.h>
#include <cuda_fp16.h>
#include <cstdint>

#define NE      20000
#define KMAX    16
#define NTRIP   (NE * KMAX)
#define EMB     128
#define INTERM  64
#define NSPH    7
#define NOUT    128
#define MT      128
#define NTHREADS 512            // 256 consumers + 256 producers
#define CHUNKS  64              // chunks per K-half (chunk = 4 i x 16 e, K=64)
#define PITCH   136             // A/B smem row pitch (in uint32)

#define NB_FULL 304
#define NB_TAIL 80
#define GRID_MAIN (NB_FULL + NB_TAIL)

// named barrier ids
#define BFULL0  1
#define BFULL1  2
#define BEMPTY0 3
#define BEMPTY1 4
#define BPROD   5

typedef unsigned long long ull;

// ---------------- persistent device scratch ----------------
__device__ int      d_trip[NTRIP];
__device__ int      d_is64;
__device__ uint32_t d_Wimg[128 * 4096];         // fp16x2 B tiles [32 kp x 128 o] per K=64 chunk
__device__ float    d_rbfT[INTERM * NSPH * NE]; // rbf transposed [i][s][e]
__device__ float    d_sumk[(size_t)NE * NSPH * EMB];

// ---------------- helpers ----------------
__device__ __forceinline__ uint32_t smem_u32(const void* p) {
    uint32_t a;
    asm("{ .reg .u64 t; cvta.to.shared.u64 t, %1; cvt.u32.u64 %0, t; }" : "=r"(a) : "l"(p));
    return a;
}
__device__ __forceinline__ ull pack2(float x, float y) {
    ull r; asm("mov.b64 %0, {%1,%2};" : "=l"(r) : "f"(x), "f"(y)); return r;
}
__device__ __forceinline__ void unpack2(ull v, float& x, float& y) {
    asm("mov.b64 {%0,%1}, %2;" : "=f"(x), "=f"(y) : "l"(v));
}
__device__ __forceinline__ ull ffma2(ull a, ull b, ull c) {
    ull d; asm("fma.rn.f32x2 %0, %1, %2, %3;" : "=l"(d) : "l"(a), "l"(b), "l"(c)); return d;
}
__device__ __forceinline__ ull mul2(ull a, ull b) {
    ull d; asm("mul.rn.f32x2 %0, %1, %2;" : "=l"(d) : "l"(a), "l"(b)); return d;
}
__device__ __forceinline__ uint32_t packh2(float lo, float hi) {
    __half2 h = __floats2half2_rn(lo, hi);
    return *(uint32_t*)&h;
}
__device__ __forceinline__ void cp_async16(uint32_t dst, const void* src) {
    asm volatile("cp.async.cg.shared.global [%0], [%1], 16;" :: "r"(dst), "l"(src) : "memory");
}
#define CP_COMMIT() asm volatile("cp.async.commit_group;" ::: "memory")
#define CP_WAIT0()  asm volatile("cp.async.wait_group 0;" ::: "memory")
#define BARS(id, cnt) asm volatile("bar.sync %0, %1;"   :: "r"(id), "r"(cnt) : "memory")
#define BARA(id, cnt) asm volatile("bar.arrive %0, %1;" :: "r"(id), "r"(cnt) : "memory")

#define MMA_F16(d, a, b0, b1)                                                  \
    asm volatile("mma.sync.aligned.m16n8k16.row.col.f32.f16.f16.f32 "          \
        "{%0,%1,%2,%3}, {%4,%5,%6,%7}, {%8,%9}, {%0,%1,%2,%3};"                \
        : "+f"((d)[0]), "+f"((d)[1]), "+f"((d)[2]), "+f"((d)[3])               \
        : "r"((a)[0]), "r"((a)[1]), "r"((a)[2]), "r"((a)[3]),                  \
          "r"(b0), "r"(b1))

// ---------------- prologue kernels ----------------
__global__ void detect_kernel(const void* idr, const void* kix, int n) {
    __shared__ int bad;
    if (threadIdx.x == 0) bad = 0;
    __syncthreads();
    int cnt = n < 2048 ? n : 2048;
    const long long* a = (const long long*)idr;
    const long long* b = (const long long*)kix;
    for (int t = threadIdx.x; t < cnt; t += blockDim.x) {
        long long v = a[t], w = b[t];
        if (v < 0 || v >= NE || w < 0 || w >= KMAX) bad = 1;
    }
    __syncthreads();
    if (threadIdx.x == 0) d_is64 = bad ? 0 : 1;
}

__global__ void build_idx_kernel(const void* idr, const void* kix, int n) {
    int t = blockIdx.x * blockDim.x + threadIdx.x;
    if (t >= n) return;
    int e, k;
    if (d_is64) {
        e = (int)((const long long*)idr)[t];
        k = (int)((const long long*)kix)[t];
    } else {
        e = ((const int*)idr)[t];
        k = ((const int*)kix)[t];
    }
    if (e >= 0 && e < NE && k >= 0 && k < KMAX) d_trip[e * KMAX + k] = t;
}

// merged prep: sumk, Wimg(fp16), rbfT (tiled transpose), zero-out
#define NB_SUMK 10000
#define NB_WIMG 128
#define NB_RBFT 8750            // 14 x 625 tiles of 32x32
#define NB_ZERO 2500
#define GRID_PREP (NB_SUMK + NB_WIMG + NB_RBFT + NB_ZERO)
__global__ __launch_bounds__(256)
void prep_kernel(const float* __restrict__ W,
                 const float* __restrict__ rbf,
                 const float* __restrict__ sph,
                 const float* __restrict__ m,
                 float* __restrict__ out) {
    __shared__ float tile[32][33];
    __shared__ float ssph[2][112];
    __shared__ int strip[2][16];
    int bid = blockIdx.x;
    if (bid < NB_SUMK) {
        const int which = threadIdx.x >> 7;
        const int e = threadIdx.x & 127;
        const int edge = bid * 2 + which;
        if (e < 112) ssph[which][e] = sph[(size_t)edge * 112 + e];
        if (e < 16) {
            int tr = d_trip[edge * KMAX + e];
            strip[which][e] = (tr < 0) ? 0 : (tr >= NTRIP ? NTRIP - 1 : tr);
        }
        __syncthreads();
        float acc[NSPH];
        #pragma unroll
        for (int s = 0; s < NSPH; ++s) acc[s] = 0.f;
        #pragma unroll
        for (int k = 0; k < KMAX; ++k) {
            float mv = m[(size_t)strip[which][k] * EMB + e];
            #pragma unroll
            for (int s = 0; s < NSPH; ++s) acc[s] = fmaf(ssph[which][s * 16 + k], mv, acc[s]);
        }
        #pragma unroll
        for (int s = 0; s < NSPH; ++s)
            d_sumk[(size_t)edge * (NSPH * EMB) + s * EMB + e] = acc[s];
    } else if (bid < NB_SUMK + NB_WIMG) {
        int cg = bid - NB_SUMK;            // 0..127
        int kh = cg >> 6, c = cg & 63;
        uint32_t* dst = d_Wimg + (size_t)cg * 4096;
        #pragma unroll
        for (int jj = 0; jj < 16; ++jj) {
            int idx = threadIdx.x + 256 * jj;   // kp*128 + o
            int kp = idx >> 7, o = idx & 127;
            int e0 = (kh * 4 + (c >> 4)) * 16 + 2 * (kp & 7);
            int i  = 4 * (c & 15) + (kp >> 3);
            float v0 = W[(size_t)e0 * (INTERM * NOUT) + i * NOUT + o];
            float v1 = W[(size_t)(e0 + 1) * (INTERM * NOUT) + i * NOUT + o];
            dst[idx] = packh2(v0, v1);
        }
    } else if (bid < NB_SUMK + NB_WIMG + NB_RBFT) {
        int t = bid - NB_SUMK - NB_WIMG;
        int tr_ = t / 625, te = t - tr_ * 625;
        int cc0 = tr_ * 32, ee0 = te * 32;
        #pragma unroll
        for (int jj = 0; jj < 4; ++jj) {
            int idx = threadIdx.x + 256 * jj;
            int le = idx >> 5, lc = idx & 31;
            tile[le][lc] = rbf[(size_t)(ee0 + le) * (INTERM * NSPH) + cc0 + lc];
        }
        __syncthreads();
        #pragma unroll
        for (int jj = 0; jj < 4; ++jj) {
            int idx = threadIdx.x + 256 * jj;
            int lc = idx >> 5, le = idx & 31;
            d_rbfT[(size_t)(cc0 + lc) * NE + ee0 + le] = tile[le][lc];
        }
    } else {
        int i = (bid - NB_SUMK - NB_WIMG - NB_RBFT) * 256 + threadIdx.x;
        if (i < NE * NOUT / 4)
            ((float4*)out)[i] = make_float4(0.f, 0.f, 0.f, 0.f);
    }
}

// ---------------- main fused kernel (warp-specialized) ----------------
#define F_RB    0                          // 2 x 3584 floats (producer-private)
#define F_A0    7168
#define F_A1    (F_A0 + 32 * PITCH)
#define F_B0    (F_A1 + 32 * PITCH)
#define F_B1    (F_B0 + 32 * PITCH)
#define SMEM_FLOATS (F_B1 + 32 * PITCH)    // 24576
#define SMEM_BYTES  (SMEM_FLOATS * 4)      // 98304

__global__ __launch_bounds__(NTHREADS, 1)
void fused_mma_kernel(float* __restrict__ out) {
    extern __shared__ float sm[];

    const int tid = threadIdx.x;
    const int bid = blockIdx.x;

    // ---- work descriptor ----
    int mtile, kh, c0, nch;
    if (bid < NB_FULL) {
        mtile = bid >> 1; kh = bid & 1; c0 = 0; nch = CHUNKS;
    } else {
        int t = bid - NB_FULL;
        int unit = t >> 3;
        mtile = 152 + (unit >> 1);
        kh = unit & 1;
        c0 = (t & 7) * 8;
        nch = 8;
    }
    const int cend = c0 + nch;
    const int n0 = mtile * MT;

    if (tid >= 256) {
        // ================= PRODUCER (threads 256..511) =================
        const int pt = tid - 256;
        const int n = pt & 127, h2 = pt >> 7;
        int nglob = n0 + n; if (nglob >= NE) nglob = NE - 1;

        ull sk[2][NSPH][2];

        auto loadSk = [&](int gl) {
            #pragma unroll
            for (int hh = 0; hh < 2; ++hh) {
                const int ebase = (kh * 4 + gl) * 16 + (2 * h2 + hh) * 4;
                const float* p = d_sumk + (size_t)nglob * (NSPH * EMB) + ebase;
                #pragma unroll
                for (int s = 0; s < NSPH; ++s) {
                    float4 v = *(const float4*)(p + s * EMB);
                    sk[hh][s][0] = pack2(v.x, v.y);
                    sk[hh][s][1] = pack2(v.z, v.w);
                }
            }
        };

        auto buildA = [&](int cn) {
            uint32_t* As = (uint32_t*)(sm + ((cn & 1) ? F_A1 : F_A0));
            const float* rb = sm + F_RB + (cn & 1) * 3584;
            #pragma unroll
            for (int i2 = 0; i2 < 4; ++i2) {
                ull rr[NSPH];
                #pragma unroll
                for (int s = 0; s < NSPH; ++s) {
                    float v = rb[(i2 * 7 + s) * 128 + n];
                    rr[s] = pack2(v, v);
                }
                #pragma unroll
                for (int hh = 0; hh < 2; ++hh) {
                    ull a0 = mul2(rr[0], sk[hh][0][0]);
                    ull a1 = mul2(rr[0], sk[hh][0][1]);
                    #pragma unroll
                    for (int s = 1; s < NSPH; ++s) {
                        a0 = ffma2(rr[s], sk[hh][s][0], a0);
                        a1 = ffma2(rr[s], sk[hh][s][1], a1);
                    }
                    float f0, f1, f2, f3;
                    unpack2(a0, f0, f1); unpack2(a1, f2, f3);
                    int kp0 = i2 * 8 + (2 * h2 + hh) * 2;
                    As[kp0 * PITCH + n]       = packh2(f0, f1);
                    As[(kp0 + 1) * PITCH + n] = packh2(f2, f3);
                }
            }
        };

        auto copyB = [&](int cn) {
            const uint32_t* src = d_Wimg + (size_t)(kh * 64 + cn) * 4096;
            uint32_t Bs = smem_u32(sm + ((cn & 1) ? F_B1 : F_B0));
            #pragma unroll
            for (int jj = 0; jj < 4; ++jj) {
                int fidx = pt + 256 * jj;
                int row = fidx >> 5, c4 = fidx & 31;
                cp_async16(Bs + (uint32_t)(row * PITCH + c4 * 4) * 4, src + fidx * 4);
            }
        };
        auto stageRb = [&](int cn) {
            const int j = cn & 15;
            uint32_t dst = smem_u32(sm + F_RB + (cn & 1) * 3584);
            #pragma unroll
            for (int jj = 0; jj < 4; ++jj) {
                int idx = pt + 256 * jj;
                if (idx < 896) {
                    int row = idx >> 5, c4 = idx & 31;
                    const float* src = d_rbfT + (size_t)(28 * j + row) * NE + n0 + c4 * 4;
                    cp_async16(dst + (uint32_t)(row * 128 + c4 * 4) * 4, src);
                }
            }
        };

        // init: sk + rb for first two chunks
        loadSk(c0 >> 4);
        stageRb(c0);
        if (c0 + 1 < cend) stageRb(c0 + 1);
        CP_COMMIT(); CP_WAIT0();
        BARS(BPROD, 256);                    // rb visible to all producers

        for (int c = c0; c < cend; ++c) {
            if ((c & 15) == 0 && c > c0) loadSk(c >> 4);
            if (c >= c0 + 2) BARS(BEMPTY0 + (c & 1), 512);   // A/B buf free
            buildA(c);                        // reads rb[c&1], writes A[c&1]
            copyB(c);                         // cp.async into B[c&1]
            BARS(BPROD, 256);                 // all producers done reading rb[c&1]
            if (c + 2 < cend) stageRb(c + 2); // overwrite rb[c&1]
            CP_COMMIT(); CP_WAIT0();          // B(c) + rb(c+2) landed (this thread)
            BARA(BFULL0 + (c & 1), 512);      // publish buffer c&1
        }
    } else {
        // ================= CONSUMER (threads 0..255) =================
        const int warp = tid >> 5, lane = tid & 31;
        const int wm = (warp >> 2) * 64, wn = (warp & 3) * 32;
        const int q = lane >> 2, r = lane & 3;

        float acc[4][4][4];
        #pragma unroll
        for (int mi = 0; mi < 4; ++mi)
            #pragma unroll
            for (int ni = 0; ni < 4; ++ni)
                #pragma unroll
                for (int v = 0; v < 4; ++v) acc[mi][ni][v] = 0.f;

        for (int c = c0; c < cend; ++c) {
            const int p = c & 1;
            BARS(BFULL0 + p, 512);            // wait for A/B of chunk c

            const uint32_t* Au = (const uint32_t*)(sm + (p ? F_A1 : F_A0));
            const uint32_t* Bu = (const uint32_t*)(sm + (p ? F_B1 : F_B0));
            #pragma unroll
            for (int ks = 0; ks < 4; ++ks) {
                const int kp = ks * 8;
                uint32_t a[4][4];
                #pragma unroll
                for (int mi = 0; mi < 4; ++mi) {
                    int base = (kp + r) * PITCH + wm + mi * 16 + q;
                    a[mi][0] = Au[base];
                    a[mi][1] = Au[base + 8];
                    a[mi][2] = Au[base + 4 * PITCH];
                    a[mi][3] = Au[base + 4 * PITCH + 8];
                }
                #pragma unroll
                for (int ni = 0; ni < 4; ++ni) {
                    uint32_t b0 = Bu[(kp + r) * PITCH + wn + ni * 8 + q];
                    uint32_t b1 = Bu[(kp + r + 4) * PITCH + wn + ni * 8 + q];
                    #pragma unroll
                    for (int mi = 0; mi < 4; ++mi)
                        MMA_F16(acc[mi][ni], a[mi], b0, b1);
                }
            }

            BARA(BEMPTY0 + p, 512);           // release buffer c&1
        }

        // ---- epilogue: atomic add partial (split-K) ----
        #pragma unroll
        for (int mi = 0; mi < 4; ++mi) {
            int row0 = n0 + wm + mi * 16 + q;
            int row1 = row0 + 8;
            #pragma unroll
            for (int ni = 0; ni < 4; ++ni) {
                int col = wn + ni * 8 + 2 * r;
                if (row0 < NE) {
                    atomicAdd(&out[(size_t)row0 * NOUT + col],     acc[mi][ni][0]);
                    atomicAdd(&out[(size_t)row0 * NOUT + col + 1], acc[mi][ni][1]);
                }
                if (row1 < NE) {
                    atomicAdd(&out[(size_t)row1 * NOUT + col],     acc[mi][ni][2]);
                    atomicAdd(&out[(size_t)row1 * NOUT + col + 1], acc[mi][ni][3]);
                }
            }
        }
    }
}

extern "C" void kernel_launch(void* const* d_in, const int* in_sizes, int n_in,
                              void* d_out, int out_size) {
    const float *rbf = 0, *sph = 0, *m = 0, *weight = 0;
    const void *idr = 0, *kix = 0;
    for (int i = 0; i < n_in; ++i) {
        long long sz = in_sizes[i];
        if      (sz == (long long)NE * INTERM * NSPH)  rbf = (const float*)d_in[i];
        else if (sz == (long long)NE * NSPH * KMAX)    sph = (const float*)d_in[i];
        else if (sz == (long long)NTRIP * EMB)         m = (const float*)d_in[i];
        else if (sz == (long long)EMB * INTERM * NOUT) weight = (const float*)d_in[i];
        else if (sz == (long long)NTRIP) { if (!idr) idr = d_in[i]; else kix = d_in[i]; }
    }
    float* out = (float*)d_out;

    cudaFuncSetAttribute(fused_mma_kernel,
                         cudaFuncAttributeMaxDynamicSharedMemorySize, SMEM_BYTES);

    detect_kernel<<<1, 256>>>(idr, kix, NTRIP);
    build_idx_kernel<<<(NTRIP + 255) / 256, 256>>>(idr, kix, NTRIP);
    prep_kernel<<<GRID_PREP, 256>>>(weight, rbf, sph, m, out);
    fused_mma_kernel<<<GRID_MAIN, NTHREADS, SMEM_BYTES>>>(out);
}